// round 9
// baseline (speedup 1.0000x reference)
#include <cuda_runtime.h>

#define MB 128
#define KS 64
#define DD 8
#define HH 128
#define NST 5
#define TT 6

typedef unsigned long long u64;
typedef unsigned int u32;

// ---------------- folded weights ----------------
// g_Wpk: 12 halves of 64x128, k-pair packed: [half][(k&63)/2 * 256 + col*2 + (k&1)]
// half order: 0,1: Wq 'a' | 2,3: Wq 'b' | 4,5: Wq 'self' | 6,7: W2a | 8,9: W2b | 10,11: W3
__device__ float g_Wpk[12*8192];
__device__ float g_bq [384];
__device__ float g_b2 [HH];
__device__ float g_b3 [HH];

// ---------------- f32x2 helpers ----------------
__device__ __forceinline__ u64 pk2(float lo, float hi) {
    u64 d; asm("mov.b64 %0, {%1, %2};" : "=l"(d) : "f"(lo), "f"(hi)); return d;
}
__device__ __forceinline__ void upk2(u64 v, float& lo, float& hi) {
    asm("mov.b64 {%0, %1}, %2;" : "=f"(lo), "=f"(hi) : "l"(v));
}
__device__ __forceinline__ u64 fma2(u64 a, u64 b, u64 c) {
    u64 d; asm("fma.rn.f32x2 %0, %1, %2, %3;" : "=l"(d) : "l"(a), "l"(b), "l"(c)); return d;
}
__device__ __forceinline__ u64 add2(u64 a, u64 b) {
    u64 d; asm("add.rn.f32x2 %0, %1, %2;" : "=l"(d) : "l"(a), "l"(b)); return d;
}

// ---------------- merged prep kernel ----------------
__device__ __forceinline__ float wc1_at(int k, int c,
        const float* __restrict__ self_w1, const float* __restrict__ inter_w1) {
    if (c < 128) return self_w1[k*128 + c];
    if (c < 256) return inter_w1[k*128 + (c - 128)];
    return inter_w1[(128 + k)*128 + (c - 256)];
}

#define PB_FOLD0  128
#define PB_BQ     512
#define PB_B23    513
#define PB_TGT0   514
#define PB_TOTAL  (514 + 854)

__global__ __launch_bounds__(384)
void prep(const float* __restrict__ gt,
          const float* __restrict__ enc_w2,  const float* __restrict__ enc_b2,
          const float* __restrict__ self_w1, const float* __restrict__ self_b1,
          const float* __restrict__ self_w2, const float* __restrict__ self_b2,
          const float* __restrict__ inter_w1,
          const float* __restrict__ inter_w2, const float* __restrict__ inter_b2,
          const float* __restrict__ upd_w1,  const float* __restrict__ upd_b1,
          const float* __restrict__ upd_w2,  const float* __restrict__ upd_b2,
          const float* __restrict__ dec_w1,  const float* __restrict__ dec_b1,
          float* __restrict__ out) {
    const int bid = blockIdx.x;
    const int tx  = threadIdx.x;
    __shared__ float arow[128];

    if (bid < PB_FOLD0) {                       // Wq rows
        int k = bid;
        if (tx < 128) arow[tx] = enc_w2[k*128 + tx];
        __syncthreads();
        float acc = 0.f;
        #pragma unroll 8
        for (int kk = 0; kk < 128; kk++) acc += arow[kk] * wc1_at(kk, tx, self_w1, inter_w1);
        int slice = tx >> 7;                    // 0:self 1:a 2:b
        int base  = (slice == 0) ? 4 : (slice == 1) ? 0 : 2;
        int half  = base + (k >> 6);
        int kk6   = k & 63;
        g_Wpk[half*8192 + (kk6 >> 1)*256 + (tx & 127)*2 + (kk6 & 1)] = acc;
    } else if (bid < PB_BQ) {                   // W2a / W2b / W3 rows
        int which = (bid - PB_FOLD0) >> 7;
        int k     = (bid - PB_FOLD0) & 127;
        const float *A, *Bm;
        if (which == 0)      { A = self_w2;  Bm = upd_w1; }
        else if (which == 1) { A = inter_w2; Bm = upd_w1 + 128*128; }
        else                 { A = upd_w2;   Bm = dec_w1; }
        if (tx < 128) arow[tx] = A[k*128 + tx];
        __syncthreads();
        if (tx < 128) {
            float acc = 0.f;
            #pragma unroll 16
            for (int kk = 0; kk < 128; kk++) acc += arow[kk] * Bm[kk*128 + tx];
            int half = 6 + 2*which + (k >> 6);
            int kk6  = k & 63;
            g_Wpk[half*8192 + (kk6 >> 1)*256 + tx*2 + (kk6 & 1)] = acc;
        }
    } else if (bid == PB_BQ) {                  // bq
        if (tx < 128) arow[tx] = enc_b2[tx];
        __syncthreads();
        float acc = (tx < 128) ? self_b1[tx] : 0.f;
        #pragma unroll 16
        for (int kk = 0; kk < 128; kk++) acc += arow[kk] * wc1_at(kk, tx, self_w1, inter_w1);
        g_bq[tx] = acc;
    } else if (bid == PB_B23) {                 // b2, b3
        if (tx < 128) {
            float a2 = upd_b1[tx], a3 = dec_b1[tx];
            #pragma unroll 16
            for (int kk = 0; kk < 128; kk++) {
                a2 += self_b2[kk]  * upd_w1[kk*128 + tx]
                    + inter_b2[kk] * upd_w1[(128 + kk)*128 + tx];
                a3 += upd_b2[kk]   * dec_w1[kk*128 + tx];
            }
            g_b2[tx] = a2; g_b3[tx] = a3;
        }
    } else {                                    // targets copy
        int o = (bid - PB_TGT0) * 384 + tx;
        if (o < MB*NST*KS*DD) {
            int b  = o / (NST*KS*DD);
            int r  = o % (NST*KS*DD);
            int t  = r / (KS*DD);
            int kd = r % (KS*DD);
            out[MB*NST*KS*DD + o] = gt[b*(TT*KS*DD) + (t + 1)*(KS*DD) + kd];
        }
    }
}

// ---------------- smem layout (floats) ----------------
#define OFF_H   0
#define OFF_A   8192
#define OFF_B   16384
#define RNG0    24576
#define OFF_P   49152
#define OFF_WDP (OFF_P  + 512)
#define OFF_WE1 (OFF_WDP+ 1024)
#define OFF_BQ  (OFF_WE1+ 1024)
#define OFF_B2  (OFF_BQ + 384)
#define OFF_B3  (OFF_B2 + 128)
#define OFF_EB1 (OFF_B3 + 128)
#define OFF_IB1 (OFF_EB1+ 128)
#define OFF_DB2 (OFF_IB1+ 128)
#define SM_FLOATS (OFF_DB2 + 8)
#define SM_BYTES  (SM_FLOATS*4)

// ---------------- cp.async weight pipeline (1024 threads) ----------------
__device__ __forceinline__ void kick(float* slot_ptr, const float* __restrict__ src, int tx) {
    u32 sbase = (u32)__cvta_generic_to_shared(slot_ptr);
    #pragma unroll
    for (int t = 0; t < 2; t++) {
        int lin = t*1024 + tx;
        asm volatile("cp.async.cg.shared.global [%0], [%1], 16;"
                     :: "r"(sbase + (u32)(lin*16)), "l"(src + lin*4) : "memory");
    }
    asm volatile("cp.async.commit_group;" ::: "memory");
}

__device__ __forceinline__ const float* pipe_adv(float* ring, int& ph, int& slot, int tx) {
    asm volatile("cp.async.wait_group 1;" ::: "memory");
    __syncthreads();
    int nh = ph + 2; if (nh >= 12) nh -= 12;
    kick(ring + ((slot + 2) % 3) * 8192, g_Wpk + nh*8192, tx);
    const float* cur = ring + slot * 8192;
    ph = (ph + 1 == 12) ? 0 : ph + 1;
    slot = (slot + 1) % 3;
    return cur;
}

// ---------------- GEMM building blocks (1024 threads: 8 rows x 1 col each) ----------------
__device__ __forceinline__ void ginit(u64 acc[8]) {
    #pragma unroll
    for (int i = 0; i < 8; i++) acc[i] = 0ULL;
}

// acc += A(64 rows x 64-k slice) @ Wpacked(64x128); sA_ pre-offset by k0
__device__ __forceinline__ void gacc_h(u64 acc[8], const float* sA_,
                                       const float* sW_, int tx) {
    const int rg = tx >> 7;          // 0..7 (8 rows each)
    const int cg = tx & 127;         // 1 col
    const float* Wp = sW_ + cg*2;
    const float* Ap = sA_ + rg*8*128;
    #pragma unroll 4
    for (int k4 = 0; k4 < 16; k4++) {
        u64 w0 = *reinterpret_cast<const u64*>(Wp + (2*k4)*256);     // k=4k4,4k4+1
        u64 w1 = *reinterpret_cast<const u64*>(Wp + (2*k4+1)*256);   // k=4k4+2,+3
        #pragma unroll
        for (int i = 0; i < 8; i++) {
            ulonglong2 av = *reinterpret_cast<const ulonglong2*>(Ap + i*128 + k4*4);
            acc[i] = fma2(av.x, w0, acc[i]);
            acc[i] = fma2(av.y, w1, acc[i]);
        }
    }
}

__device__ __forceinline__ void gepi(u64 acc[8], const float* sbias, bool relu,
                                     float* sC, int tx) {
    const int rg = tx >> 7, cg = tx & 127;
    float bz = sbias[cg];
    #pragma unroll
    for (int i = 0; i < 8; i++) {
        float lo, hi;
        upk2(acc[i], lo, hi);
        float v = lo + hi + bz;
        if (relu) v = fmaxf(v, 0.f);
        sC[(rg*8 + i)*128 + cg] = v;
    }
}

// ---------------- pairwise, h-pair version, barrier-free, in place on sB ----
// r[j][h] = mean_i relu(a[i][h]+b[j][h]+bias[h]) = 0.5/64 * (Sa + 64*v_j + sum_i |a_i + v_j|)
// 1024 threads: hp = h-pair (64), jg (16) -> 4 j each; a streamed in chunks of 8 rows
__device__ void pairwise_fn(const float* sA_, float* sB_, const float* sIB1, int tx) {
    const int hp = tx & 63;
    const int jg = tx >> 6;               // 0..15
    const float* ab = sA_ + hp*2;
    float* bb = sB_ + jg*4*128 + hp*2;
    const u64 bias2 = *reinterpret_cast<const u64*>(sIB1 + hp*2);
    u64 vj[4], accj[4];
    #pragma unroll
    for (int t = 0; t < 4; t++) {
        vj[t] = add2(*reinterpret_cast<const u64*>(bb + t*128), bias2);
        accj[t] = 0ULL;
    }
    u64 Sa = 0ULL;
    const u64 MASK = 0x7FFFFFFF7FFFFFFFULL;
    #pragma unroll 1
    for (int c = 0; c < 8; c++) {          // 8 chunks of 8 rows
        u64 ap[8];
        #pragma unroll
        for (int i = 0; i < 8; i++) {
            ap[i] = *reinterpret_cast<const u64*>(ab + (c*8 + i)*128);
            Sa = add2(Sa, ap[i]);
        }
        #pragma unroll
        for (int t = 0; t < 4; t++) {
            u64 v = vj[t], s = accj[t];
            #pragma unroll
            for (int i = 0; i < 8; i++) {
                u64 x = add2(ap[i], v);
                x &= MASK;
                s = add2(s, x);
            }
            accj[t] = s;
        }
    }
    #pragma unroll
    for (int t = 0; t < 4; t++) {
        float slo, shi, alo, ahi, vlo, vhi;
        upk2(accj[t], slo, shi); upk2(Sa, alo, ahi); upk2(vj[t], vlo, vhi);
        float rlo = (alo + 64.f*vlo + slo) * (0.5f/64.f);
        float rhi = (ahi + 64.f*vhi + shi) * (0.5f/64.f);
        *reinterpret_cast<u64*>(bb + t*128) = pk2(rlo, rhi);
    }
}

// pred = Hd @ dec_w2 + db2 -> sP and global out (512 active threads)
__device__ __forceinline__ void decf(const float* sHd, const float* sWdp, const float* sDB2,
                                     float* sP, float* __restrict__ out,
                                     int b, int step, int tx) {
    if (tx >= 512) return;
    const int m = tx >> 3;
    const int d = tx & 7;
    u64 acc = 0ULL;
    const float* hp = sHd + m*128;
    const float* wp = sWdp + d*2;
    #pragma unroll 8
    for (int k2 = 0; k2 < 64; k2++)
        acc = fma2(*reinterpret_cast<const u64*>(hp + 2*k2),
                   *reinterpret_cast<const u64*>(wp + k2*16), acc);
    float lo, hi; upk2(acc, lo, hi);
    float val = lo + hi + sDB2[d];
    sP[m*8 + d] = val;
    out[((b*NST + step)*KS + m)*DD + d] = val;
}

// sO = relu(sP(64x8) @ We1(8x128) + eb1); 8 rows x 1 col per thread
__device__ __forceinline__ void enc1(const float* sPin, const float* sWe1,
                                     const float* sEB1, float* sO, int tx) {
    const int r0 = (tx >> 7) * 8;
    const int c0 = tx & 127;
    float w[8];
    #pragma unroll
    for (int k = 0; k < 8; k++) w[k] = sWe1[k*128 + c0];
    float bz = sEB1[c0];
    #pragma unroll
    for (int i = 0; i < 8; i++) {
        float o = bz;
        #pragma unroll
        for (int k = 0; k < 8; k++) o += sPin[(r0+i)*8 + k] * w[k];
        sO[(r0+i)*128 + c0] = fmaxf(o, 0.f);
    }
}

// ---------------- persistent per-batch rollout ----------------
__global__ __launch_bounds__(1024, 1)
void rollout(const float* __restrict__ gt,
             const float* __restrict__ enc_w1, const float* __restrict__ enc_b1,
             const float* __restrict__ inter_b1,
             const float* __restrict__ dec_w2, const float* __restrict__ dec_b2,
             float* __restrict__ out) {
    extern __shared__ float sm[];
    float* sH   = sm + OFF_H;
    float* sA   = sm + OFF_A;
    float* sB   = sm + OFF_B;
    float* ring = sm + RNG0;
    float* sP   = sm + OFF_P;
    float* sWdp = sm + OFF_WDP;
    float* sWe1 = sm + OFF_WE1;

    const int tx = threadIdx.x;
    const int b  = blockIdx.x;

    {
        int i = tx;                                  // 1024 elems each
        sWe1[i] = enc_w1[i];
        int k = i >> 3, d = i & 7;                   // pack dec_w2 in k-pairs
        sWdp[(k >> 1)*16 + d*2 + (k & 1)] = dec_w2[i];
    }
    if (tx < 384) sm[OFF_BQ + tx] = g_bq[tx];
    if (tx < 128) {
        sm[OFF_B2  + tx] = g_b2[tx];
        sm[OFF_B3  + tx] = g_b3[tx];
        sm[OFF_EB1 + tx] = enc_b1[tx];
        sm[OFF_IB1 + tx] = inter_b1[tx];
    }
    if (tx >= 128 && tx < 136) sm[OFF_DB2 + tx - 128] = dec_b2[tx - 128];
    if (tx < 512) sP[tx] = gt[b*(TT*KS*DD) + tx];    // x0
    __syncthreads();

    enc1(sP, sWe1, sm + OFF_EB1, sH, tx);

    int ph = 0, slot = 0;
    kick(ring,        g_Wpk,        tx);
    kick(ring + 8192, g_Wpk + 8192, tx);

    #pragma unroll 1
    for (int step = 0; step < NST; step++) {
        const float* w;
        {   // a = He @ Wq_a + bq[128:256] -> sA
            u64 acc[8]; ginit(acc);
            w = pipe_adv(ring, ph, slot, tx); gacc_h(acc, sH,      w, tx);
            w = pipe_adv(ring, ph, slot, tx); gacc_h(acc, sH + 64, w, tx);
            gepi(acc, sm + OFF_BQ + 128, false, sA, tx);
        }
        {   // b = He @ Wq_b + bq[256:384] -> sB
            u64 acc[8]; ginit(acc);
            w = pipe_adv(ring, ph, slot, tx); gacc_h(acc, sH,      w, tx);
            w = pipe_adv(ring, ph, slot, tx); gacc_h(acc, sH + 64, w, tx);
            gepi(acc, sm + OFF_BQ + 256, false, sB, tx);
        }
        {   // pairwise (barrier-free, ordered by pipe_adv sync) + Hself
            w = pipe_adv(ring, ph, slot, tx);      // barrier: sA/sB visible
            pairwise_fn(sA, sB, sm + OFF_IB1, tx); // r -> sB in place
            u64 acc[8]; ginit(acc);
            gacc_h(acc, sH, w, tx);
            w = pipe_adv(ring, ph, slot, tx); gacc_h(acc, sH + 64, w, tx);
            gepi(acc, sm + OFF_BQ, true, sA, tx);  // Hself -> sA
        }
        {   // Hu = relu(Hself@W2a + r@W2b + b2) -> sH
            u64 acc[8]; ginit(acc);
            w = pipe_adv(ring, ph, slot, tx); gacc_h(acc, sA,      w, tx);
            w = pipe_adv(ring, ph, slot, tx); gacc_h(acc, sA + 64, w, tx);
            w = pipe_adv(ring, ph, slot, tx); gacc_h(acc, sB,      w, tx);
            w = pipe_adv(ring, ph, slot, tx); gacc_h(acc, sB + 64, w, tx);
            gepi(acc, sm + OFF_B2, true, sH, tx);
        }
        {   // Hd = relu(Hu@W3 + b3) -> sA
            u64 acc[8]; ginit(acc);
            w = pipe_adv(ring, ph, slot, tx); gacc_h(acc, sH,      w, tx);
            w = pipe_adv(ring, ph, slot, tx); gacc_h(acc, sH + 64, w, tx);
            gepi(acc, sm + OFF_B3, true, sA, tx);
        }
        __syncthreads();
        decf(sA, sWdp, sm + OFF_DB2, sP, out, b, step, tx);
        if (step + 1 < NST) {
            __syncthreads();
            enc1(sP, sWe1, sm + OFF_EB1, sH, tx);
        }
    }
    asm volatile("cp.async.wait_all;" ::: "memory");
}

// ---------------- launch ----------------
extern "C" void kernel_launch(void* const* d_in, const int* in_sizes, int n_in,
                              void* d_out, int out_size) {
    const float* gt       = (const float*)d_in[0];
    const float* enc_w1   = (const float*)d_in[2];
    const float* enc_b1   = (const float*)d_in[3];
    const float* enc_w2   = (const float*)d_in[4];
    const float* enc_b2   = (const float*)d_in[5];
    const float* self_w1  = (const float*)d_in[6];
    const float* self_b1  = (const float*)d_in[7];
    const float* self_w2  = (const float*)d_in[8];
    const float* self_b2  = (const float*)d_in[9];
    const float* inter_w1 = (const float*)d_in[10];
    const float* inter_b1 = (const float*)d_in[11];
    const float* inter_w2 = (const float*)d_in[12];
    const float* inter_b2 = (const float*)d_in[13];
    const float* upd_w1   = (const float*)d_in[14];
    const float* upd_b1   = (const float*)d_in[15];
    const float* upd_w2   = (const float*)d_in[16];
    const float* upd_b2   = (const float*)d_in[17];
    const float* dec_w1   = (const float*)d_in[18];
    const float* dec_b1   = (const float*)d_in[19];
    const float* dec_w2   = (const float*)d_in[20];
    const float* dec_b2   = (const float*)d_in[21];
    float* out = (float*)d_out;

    cudaFuncSetAttribute(rollout, cudaFuncAttributeMaxDynamicSharedMemorySize, SM_BYTES);

    prep<<<PB_TOTAL, 384>>>(gt, enc_w2, enc_b2, self_w1, self_b1, self_w2, self_b2,
                            inter_w1, inter_w2, inter_b2, upd_w1, upd_b1,
                            upd_w2, upd_b2, dec_w1, dec_b1, out);

    rollout<<<MB, 1024, SM_BYTES>>>(gt, enc_w1, enc_b1, inter_b1, dec_w2, dec_b2, out);
}

// round 11
// speedup vs baseline: 1.3063x; 1.3063x over previous
#include <cuda_runtime.h>

#define MB 128
#define KS 64
#define DD 8
#define HH 128
#define NST 5
#define TT 6

typedef unsigned long long u64;
typedef unsigned int u32;

// ---------------- folded weights ----------------
// g_Wpk: 12 halves of 64x128, k-pair packed: [half][(k&63)/2 * 256 + col*2 + (k&1)]
// half order: 0,1: Wq 'a' | 2,3: Wq 'b' | 4,5: Wq 'self' | 6,7: W2a | 8,9: W2b | 10,11: W3
__device__ float g_Wpk[12*8192];
__device__ float g_bq [384];
__device__ float g_b2 [HH];
__device__ float g_b3 [HH];

// ---------------- f32x2 helpers ----------------
__device__ __forceinline__ u64 pk2(float lo, float hi) {
    u64 d; asm("mov.b64 %0, {%1, %2};" : "=l"(d) : "f"(lo), "f"(hi)); return d;
}
__device__ __forceinline__ void upk2(u64 v, float& lo, float& hi) {
    asm("mov.b64 {%0, %1}, %2;" : "=f"(lo), "=f"(hi) : "l"(v));
}
__device__ __forceinline__ u64 fma2(u64 a, u64 b, u64 c) {
    u64 d; asm("fma.rn.f32x2 %0, %1, %2, %3;" : "=l"(d) : "l"(a), "l"(b), "l"(c)); return d;
}
__device__ __forceinline__ u64 add2(u64 a, u64 b) {
    u64 d; asm("add.rn.f32x2 %0, %1, %2;" : "=l"(d) : "l"(a), "l"(b)); return d;
}

// ---------------- merged prep kernel ----------------
__device__ __forceinline__ float wc1_at(int k, int c,
        const float* __restrict__ self_w1, const float* __restrict__ inter_w1) {
    if (c < 128) return self_w1[k*128 + c];
    if (c < 256) return inter_w1[k*128 + (c - 128)];
    return inter_w1[(128 + k)*128 + (c - 256)];
}

#define PB_FOLD0  128
#define PB_BQ     512
#define PB_B23    513
#define PB_TGT0   514
#define PB_TOTAL  (514 + 854)

__global__ __launch_bounds__(384)
void prep(const float* __restrict__ gt,
          const float* __restrict__ enc_w2,  const float* __restrict__ enc_b2,
          const float* __restrict__ self_w1, const float* __restrict__ self_b1,
          const float* __restrict__ self_w2, const float* __restrict__ self_b2,
          const float* __restrict__ inter_w1,
          const float* __restrict__ inter_w2, const float* __restrict__ inter_b2,
          const float* __restrict__ upd_w1,  const float* __restrict__ upd_b1,
          const float* __restrict__ upd_w2,  const float* __restrict__ upd_b2,
          const float* __restrict__ dec_w1,  const float* __restrict__ dec_b1,
          float* __restrict__ out) {
    const int bid = blockIdx.x;
    const int tx  = threadIdx.x;
    __shared__ float arow[128];

    if (bid < PB_FOLD0) {                       // Wq rows
        int k = bid;
        if (tx < 128) arow[tx] = enc_w2[k*128 + tx];
        __syncthreads();
        float acc = 0.f;
        #pragma unroll 8
        for (int kk = 0; kk < 128; kk++) acc += arow[kk] * wc1_at(kk, tx, self_w1, inter_w1);
        int slice = tx >> 7;                    // 0:self 1:a 2:b
        int base  = (slice == 0) ? 4 : (slice == 1) ? 0 : 2;
        int half  = base + (k >> 6);
        int kk6   = k & 63;
        g_Wpk[half*8192 + (kk6 >> 1)*256 + (tx & 127)*2 + (kk6 & 1)] = acc;
    } else if (bid < PB_BQ) {                   // W2a / W2b / W3 rows
        int which = (bid - PB_FOLD0) >> 7;
        int k     = (bid - PB_FOLD0) & 127;
        const float *A, *Bm;
        if (which == 0)      { A = self_w2;  Bm = upd_w1; }
        else if (which == 1) { A = inter_w2; Bm = upd_w1 + 128*128; }
        else                 { A = upd_w2;   Bm = dec_w1; }
        if (tx < 128) arow[tx] = A[k*128 + tx];
        __syncthreads();
        if (tx < 128) {
            float acc = 0.f;
            #pragma unroll 16
            for (int kk = 0; kk < 128; kk++) acc += arow[kk] * Bm[kk*128 + tx];
            int half = 6 + 2*which + (k >> 6);
            int kk6  = k & 63;
            g_Wpk[half*8192 + (kk6 >> 1)*256 + tx*2 + (kk6 & 1)] = acc;
        }
    } else if (bid == PB_BQ) {                  // bq
        if (tx < 128) arow[tx] = enc_b2[tx];
        __syncthreads();
        float acc = (tx < 128) ? self_b1[tx] : 0.f;
        #pragma unroll 16
        for (int kk = 0; kk < 128; kk++) acc += arow[kk] * wc1_at(kk, tx, self_w1, inter_w1);
        g_bq[tx] = acc;
    } else if (bid == PB_B23) {                 // b2, b3
        if (tx < 128) {
            float a2 = upd_b1[tx], a3 = dec_b1[tx];
            #pragma unroll 16
            for (int kk = 0; kk < 128; kk++) {
                a2 += self_b2[kk]  * upd_w1[kk*128 + tx]
                    + inter_b2[kk] * upd_w1[(128 + kk)*128 + tx];
                a3 += upd_b2[kk]   * dec_w1[kk*128 + tx];
            }
            g_b2[tx] = a2; g_b3[tx] = a3;
        }
    } else {                                    // targets copy
        int o = (bid - PB_TGT0) * 384 + tx;
        if (o < MB*NST*KS*DD) {
            int b  = o / (NST*KS*DD);
            int r  = o % (NST*KS*DD);
            int t  = r / (KS*DD);
            int kd = r % (KS*DD);
            out[MB*NST*KS*DD + o] = gt[b*(TT*KS*DD) + (t + 1)*(KS*DD) + kd];
        }
    }
}

// ---------------- smem layout (floats) ----------------
#define OFF_H   0
#define OFF_A   8192
#define OFF_B   16384
#define RNG0    24576
#define OFF_P   49152
#define OFF_WDP (OFF_P  + 512)
#define OFF_WE1 (OFF_WDP+ 1024)
#define OFF_BQ  (OFF_WE1+ 1024)
#define OFF_B2  (OFF_BQ + 384)
#define OFF_B3  (OFF_B2 + 128)
#define OFF_EB1 (OFF_B3 + 128)
#define OFF_IB1 (OFF_EB1+ 128)
#define OFF_DB2 (OFF_IB1+ 128)
#define SM_FLOATS (OFF_DB2 + 8)
#define SM_BYTES  (SM_FLOATS*4)

// ---------------- cp.async weight pipeline (256 threads) ----------------
__device__ __forceinline__ void kick(float* slot_ptr, const float* __restrict__ src, int tx) {
    u32 sbase = (u32)__cvta_generic_to_shared(slot_ptr);
    #pragma unroll
    for (int t = 0; t < 8; t++) {
        int lin = t*256 + tx;            // 2048 chunks of 16B
        asm volatile("cp.async.cg.shared.global [%0], [%1], 16;"
                     :: "r"(sbase + (u32)(lin*16)), "l"(src + lin*4) : "memory");
    }
    asm volatile("cp.async.commit_group;" ::: "memory");
}

__device__ __forceinline__ const float* pipe_adv(float* ring, int& ph, int& slot, int tx) {
    asm volatile("cp.async.wait_group 1;" ::: "memory");
    __syncthreads();
    int nh = ph + 2; if (nh >= 12) nh -= 12;
    kick(ring + ((slot + 2) % 3) * 8192, g_Wpk + nh*8192, tx);
    const float* cur = ring + slot * 8192;
    ph = (ph + 1 == 12) ? 0 : ph + 1;
    slot = (slot + 1) % 3;
    return cur;
}

// ---------------- GEMM building blocks (256 threads: 8 rows x 4 cols each) ----------------
__device__ __forceinline__ void ginit(u64 acc[8][4]) {
    #pragma unroll
    for (int i = 0; i < 8; i++)
        #pragma unroll
        for (int j = 0; j < 4; j++) acc[i][j] = 0ULL;
}

// acc += A(64 rows x 64-k slice) @ Wpacked(64x128); sA_ pre-offset by k0
__device__ __forceinline__ void gacc_h(u64 acc[8][4], const float* sA_,
                                       const float* sW_, int tx) {
    const int rg = tx >> 5;          // 0..7 (8 rows each)
    const int cg = tx & 31;          // 0..31 (4 cols each)
    const float* Wp = sW_ + cg*8;
    const float* Ap = sA_ + rg*8*128;
    #pragma unroll 4
    for (int k4 = 0; k4 < 16; k4++) {
        // k-pair row 2k4 (k = 4k4, 4k4+1) and 2k4+1 (k = 4k4+2, 4k4+3)
        ulonglong2 wa0 = *reinterpret_cast<const ulonglong2*>(Wp + (2*k4)*256);      // cols c0,c0+1
        ulonglong2 wb0 = *reinterpret_cast<const ulonglong2*>(Wp + (2*k4)*256 + 4);  // cols c0+2,c0+3
        ulonglong2 wa1 = *reinterpret_cast<const ulonglong2*>(Wp + (2*k4+1)*256);
        ulonglong2 wb1 = *reinterpret_cast<const ulonglong2*>(Wp + (2*k4+1)*256 + 4);
        #pragma unroll
        for (int i = 0; i < 8; i++) {
            ulonglong2 av = *reinterpret_cast<const ulonglong2*>(Ap + i*128 + k4*4);
            acc[i][0] = fma2(av.x, wa0.x, acc[i][0]);
            acc[i][1] = fma2(av.x, wa0.y, acc[i][1]);
            acc[i][2] = fma2(av.x, wb0.x, acc[i][2]);
            acc[i][3] = fma2(av.x, wb0.y, acc[i][3]);
            acc[i][0] = fma2(av.y, wa1.x, acc[i][0]);
            acc[i][1] = fma2(av.y, wa1.y, acc[i][1]);
            acc[i][2] = fma2(av.y, wb1.x, acc[i][2]);
            acc[i][3] = fma2(av.y, wb1.y, acc[i][3]);
        }
    }
}

__device__ __forceinline__ void gepi(u64 acc[8][4], const float* sbias, bool relu,
                                     float* sC, int tx) {
    const int rg = tx >> 5, cg = tx & 31;
    float4 bz = *reinterpret_cast<const float4*>(sbias + cg*4);
    #pragma unroll
    for (int i = 0; i < 8; i++) {
        float lo, hi; float4 o;
        upk2(acc[i][0], lo, hi); o.x = lo + hi + bz.x;
        upk2(acc[i][1], lo, hi); o.y = lo + hi + bz.y;
        upk2(acc[i][2], lo, hi); o.z = lo + hi + bz.z;
        upk2(acc[i][3], lo, hi); o.w = lo + hi + bz.w;
        if (relu) {
            o.x = fmaxf(o.x, 0.f); o.y = fmaxf(o.y, 0.f);
            o.z = fmaxf(o.z, 0.f); o.w = fmaxf(o.w, 0.f);
        }
        *reinterpret_cast<float4*>(sC + (rg*8 + i)*128 + cg*4) = o;
    }
}

// ---------------- pairwise, h-pair version, barrier-free, in place on sB ----
// r[j][h] = mean_i relu(a[i][h]+b[j][h]+bias[h]) = 0.5/64 * (Sa + 64*v_j + sum_i |a_i + v_j|)
// 256 threads: hp = h-pair (64), jg (4) -> 16 j each; a streamed in chunks of 8 rows
__device__ void pairwise_fn(const float* sA_, float* sB_, const float* sIB1, int tx) {
    const int hp = tx & 63;
    const int jg = tx >> 6;               // 0..3
    const float* ab = sA_ + hp*2;
    float* bb = sB_ + jg*16*128 + hp*2;
    const u64 bias2 = *reinterpret_cast<const u64*>(sIB1 + hp*2);
    u64 vj[16], accj[16];
    #pragma unroll
    for (int t = 0; t < 16; t++) {
        vj[t] = add2(*reinterpret_cast<const u64*>(bb + t*128), bias2);
        accj[t] = 0ULL;
    }
    u64 Sa = 0ULL;
    const u64 MASK = 0x7FFFFFFF7FFFFFFFULL;
    #pragma unroll 1
    for (int c = 0; c < 8; c++) {          // 8 chunks of 8 rows
        u64 ap[8];
        #pragma unroll
        for (int i = 0; i < 8; i++) {
            ap[i] = *reinterpret_cast<const u64*>(ab + (c*8 + i)*128);
            Sa = add2(Sa, ap[i]);
        }
        #pragma unroll
        for (int t = 0; t < 16; t++) {
            u64 v = vj[t], s = accj[t];
            #pragma unroll
            for (int i = 0; i < 8; i++) {
                u64 x = add2(ap[i], v);
                x &= MASK;
                s = add2(s, x);
            }
            accj[t] = s;
        }
    }
    #pragma unroll
    for (int t = 0; t < 16; t++) {
        float slo, shi, alo, ahi, vlo, vhi;
        upk2(accj[t], slo, shi); upk2(Sa, alo, ahi); upk2(vj[t], vlo, vhi);
        float rlo = (alo + 64.f*vlo + slo) * (0.5f/64.f);
        float rhi = (ahi + 64.f*vhi + shi) * (0.5f/64.f);
        *reinterpret_cast<u64*>(bb + t*128) = pk2(rlo, rhi);
    }
}

// pred = Hd @ dec_w2 + db2 -> sP and global out (256 threads, 2 outputs each)
__device__ __forceinline__ void decf(const float* sHd, const float* sWdp, const float* sDB2,
                                     float* sP, float* __restrict__ out,
                                     int b, int step, int tx) {
    const int m  = tx >> 2;
    const int d0 = (tx & 3) * 2;
    const float* hp = sHd + m*128;
    u64 acc0 = 0ULL, acc1 = 0ULL;
    const float* wp0 = sWdp + d0*2;
    const float* wp1 = sWdp + (d0+1)*2;
    #pragma unroll 8
    for (int k2 = 0; k2 < 64; k2++) {
        u64 h2 = *reinterpret_cast<const u64*>(hp + 2*k2);
        acc0 = fma2(h2, *reinterpret_cast<const u64*>(wp0 + k2*16), acc0);
        acc1 = fma2(h2, *reinterpret_cast<const u64*>(wp1 + k2*16), acc1);
    }
    float lo, hi;
    upk2(acc0, lo, hi); float v0 = lo + hi + sDB2[d0];
    upk2(acc1, lo, hi); float v1 = lo + hi + sDB2[d0+1];
    sP[m*8 + d0] = v0; sP[m*8 + d0 + 1] = v1;
    float2 pr; pr.x = v0; pr.y = v1;
    *reinterpret_cast<float2*>(out + ((b*NST + step)*KS + m)*DD + d0) = pr;
}

// sO = relu(sP(64x8) @ We1(8x128) + eb1); 8 rows x 4 cols per thread
__device__ __forceinline__ void enc1(const float* sPin, const float* sWe1,
                                     const float* sEB1, float* sO, int tx) {
    const int r0 = (tx >> 5) * 8;
    const int c0 = (tx & 31) * 4;
    float4 w[8];
    #pragma unroll
    for (int k = 0; k < 8; k++) w[k] = *reinterpret_cast<const float4*>(sWe1 + k*128 + c0);
    float4 bz = *reinterpret_cast<const float4*>(sEB1 + c0);
    #pragma unroll
    for (int i = 0; i < 8; i++) {
        float4 o = bz;
        #pragma unroll
        for (int k = 0; k < 8; k++) {
            float a = sPin[(r0+i)*8 + k];
            o.x += a*w[k].x; o.y += a*w[k].y; o.z += a*w[k].z; o.w += a*w[k].w;
        }
        o.x = fmaxf(o.x, 0.f); o.y = fmaxf(o.y, 0.f);
        o.z = fmaxf(o.z, 0.f); o.w = fmaxf(o.w, 0.f);
        *reinterpret_cast<float4*>(sO + (r0+i)*128 + c0) = o;
    }
}

// ---------------- persistent per-batch rollout ----------------
__global__ __launch_bounds__(256, 1)
void rollout(const float* __restrict__ gt,
             const float* __restrict__ enc_w1, const float* __restrict__ enc_b1,
             const float* __restrict__ inter_b1,
             const float* __restrict__ dec_w2, const float* __restrict__ dec_b2,
             float* __restrict__ out) {
    extern __shared__ float sm[];
    float* sH   = sm + OFF_H;
    float* sA   = sm + OFF_A;
    float* sB   = sm + OFF_B;
    float* ring = sm + RNG0;
    float* sP   = sm + OFF_P;
    float* sWdp = sm + OFF_WDP;
    float* sWe1 = sm + OFF_WE1;

    const int tx = threadIdx.x;
    const int b  = blockIdx.x;

    #pragma unroll
    for (int t = 0; t < 4; t++) {
        int i = t*256 + tx;
        sWe1[i] = enc_w1[i];
        int k = i >> 3, d = i & 7;                   // pack dec_w2 in k-pairs
        sWdp[(k >> 1)*16 + d*2 + (k & 1)] = dec_w2[i];
    }
    for (int i = tx; i < 384; i += 256) sm[OFF_BQ + i] = g_bq[i];
    if (tx < 128) {
        sm[OFF_B2  + tx] = g_b2[tx];
        sm[OFF_B3  + tx] = g_b3[tx];
        sm[OFF_EB1 + tx] = enc_b1[tx];
        sm[OFF_IB1 + tx] = inter_b1[tx];
    }
    if (tx >= 128 && tx < 136) sm[OFF_DB2 + tx - 128] = dec_b2[tx - 128];
    #pragma unroll
    for (int t = 0; t < 2; t++) sP[t*256 + tx] = gt[b*(TT*KS*DD) + t*256 + tx];  // x0
    __syncthreads();

    enc1(sP, sWe1, sm + OFF_EB1, sH, tx);

    int ph = 0, slot = 0;
    kick(ring,        g_Wpk,        tx);
    kick(ring + 8192, g_Wpk + 8192, tx);

    #pragma unroll 1
    for (int step = 0; step < NST; step++) {
        const float* w;
        {   // a = He @ Wq_a + bq[128:256] -> sA
            u64 acc[8][4]; ginit(acc);
            w = pipe_adv(ring, ph, slot, tx); gacc_h(acc, sH,      w, tx);
            w = pipe_adv(ring, ph, slot, tx); gacc_h(acc, sH + 64, w, tx);
            gepi(acc, sm + OFF_BQ + 128, false, sA, tx);
        }
        {   // b = He @ Wq_b + bq[256:384] -> sB
            u64 acc[8][4]; ginit(acc);
            w = pipe_adv(ring, ph, slot, tx); gacc_h(acc, sH,      w, tx);
            w = pipe_adv(ring, ph, slot, tx); gacc_h(acc, sH + 64, w, tx);
            gepi(acc, sm + OFF_BQ + 256, false, sB, tx);
        }
        {   // pairwise (barrier-free, ordered by pipe_adv sync) + Hself
            w = pipe_adv(ring, ph, slot, tx);      // barrier: sA/sB visible
            pairwise_fn(sA, sB, sm + OFF_IB1, tx); // r -> sB in place
            u64 acc[8][4]; ginit(acc);
            gacc_h(acc, sH, w, tx);
            w = pipe_adv(ring, ph, slot, tx); gacc_h(acc, sH + 64, w, tx);
            gepi(acc, sm + OFF_BQ, true, sA, tx);  // Hself -> sA (barrier above orders vs pairwise reads)
        }
        {   // Hu = relu(Hself@W2a + r@W2b + b2) -> sH
            u64 acc[8][4]; ginit(acc);
            w = pipe_adv(ring, ph, slot, tx); gacc_h(acc, sA,      w, tx);
            w = pipe_adv(ring, ph, slot, tx); gacc_h(acc, sA + 64, w, tx);
            w = pipe_adv(ring, ph, slot, tx); gacc_h(acc, sB,      w, tx);
            w = pipe_adv(ring, ph, slot, tx); gacc_h(acc, sB + 64, w, tx);
            gepi(acc, sm + OFF_B2, true, sH, tx);
        }
        {   // Hd = relu(Hu@W3 + b3) -> sA
            u64 acc[8][4]; ginit(acc);
            w = pipe_adv(ring, ph, slot, tx); gacc_h(acc, sH,      w, tx);
            w = pipe_adv(ring, ph, slot, tx); gacc_h(acc, sH + 64, w, tx);
            gepi(acc, sm + OFF_B3, true, sA, tx);
        }
        __syncthreads();
        decf(sA, sWdp, sm + OFF_DB2, sP, out, b, step, tx);
        if (step + 1 < NST) {
            __syncthreads();
            enc1(sP, sWe1, sm + OFF_EB1, sH, tx);
        }
    }
    asm volatile("cp.async.wait_all;" ::: "memory");
}

// ---------------- launch ----------------
extern "C" void kernel_launch(void* const* d_in, const int* in_sizes, int n_in,
                              void* d_out, int out_size) {
    const float* gt       = (const float*)d_in[0];
    const float* enc_w1   = (const float*)d_in[2];
    const float* enc_b1   = (const float*)d_in[3];
    const float* enc_w2   = (const float*)d_in[4];
    const float* enc_b2   = (const float*)d_in[5];
    const float* self_w1  = (const float*)d_in[6];
    const float* self_b1  = (const float*)d_in[7];
    const float* self_w2  = (const float*)d_in[8];
    const float* self_b2  = (const float*)d_in[9];
    const float* inter_w1 = (const float*)d_in[10];
    const float* inter_b1 = (const float*)d_in[11];
    const float* inter_w2 = (const float*)d_in[12];
    const float* inter_b2 = (const float*)d_in[13];
    const float* upd_w1   = (const float*)d_in[14];
    const float* upd_b1   = (const float*)d_in[15];
    const float* upd_w2   = (const float*)d_in[16];
    const float* upd_b2   = (const float*)d_in[17];
    const float* dec_w1   = (const float*)d_in[18];
    const float* dec_b1   = (const float*)d_in[19];
    const float* dec_w2   = (const float*)d_in[20];
    const float* dec_b2   = (const float*)d_in[21];
    float* out = (float*)d_out;

    cudaFuncSetAttribute(rollout, cudaFuncAttributeMaxDynamicSharedMemorySize, SM_BYTES);

    prep<<<PB_TOTAL, 384>>>(gt, enc_w2, enc_b2, self_w1, self_b1, self_w2, self_b2,
                            inter_w1, inter_w2, inter_b2, upd_w1, upd_b1,
                            upd_w2, upd_b2, dec_w1, dec_b1, out);

    rollout<<<MB, 256, SM_BYTES>>>(gt, enc_w1, enc_b1, inter_b1, dec_w2, dec_b2, out);
}